// round 10
// baseline (speedup 1.0000x reference)
#include <cuda_runtime.h>
#include <cuda_bf16.h>
#include <cstdint>
#include <math.h>

#define B_   32
#define N_   256
#define E_   512
#define H_   8
#define D_   64
#define ID_  8
#define KDIM 512

// ---------------- device-global scratch (alloc-free), all bf16 hi/lo ----------------
__device__ __nv_bfloat16 g_xhi[(size_t)B_*N_*E_],  g_xlo[(size_t)B_*N_*E_];
__device__ __nv_bfloat16 g_wqhi[(size_t)3*E_*E_],  g_wqlo[(size_t)3*E_*E_];
__device__ __nv_bfloat16 g_wohi[(size_t)E_*E_],    g_wolo[(size_t)E_*E_];
__device__ __nv_bfloat16 g_qhi[(size_t)B_*H_*N_*D_], g_qlo[(size_t)B_*H_*N_*D_];
__device__ __nv_bfloat16 g_khi[(size_t)B_*H_*N_*D_], g_klo[(size_t)B_*H_*N_*D_];
__device__ __nv_bfloat16 g_vhi[(size_t)B_*H_*N_*D_], g_vlo[(size_t)B_*H_*N_*D_];
__device__ __nv_bfloat16 g_ohi[(size_t)B_*N_*E_],  g_olo[(size_t)B_*N_*E_];
__device__ float g_bias[(size_t)B_*H_*N_*N_];

// ================= helpers =================
__device__ __forceinline__ uint32_t smem_u32(const void* p) {
    uint32_t a;
    asm("{ .reg .u64 t; cvta.to.shared.u64 t, %1; cvt.u32.u64 %0, t; }" : "=r"(a) : "l"(p));
    return a;
}
__device__ __forceinline__ void ldsm4(uint32_t* r, uint32_t addr) {
    asm volatile("ldmatrix.sync.aligned.m8n8.x4.shared.b16 {%0,%1,%2,%3}, [%4];"
        : "=r"(r[0]), "=r"(r[1]), "=r"(r[2]), "=r"(r[3]) : "r"(addr));
}
__device__ __forceinline__ void ldsm4t(uint32_t* r, uint32_t addr) {
    asm volatile("ldmatrix.sync.aligned.m8n8.x4.trans.shared.b16 {%0,%1,%2,%3}, [%4];"
        : "=r"(r[0]), "=r"(r[1]), "=r"(r[2]), "=r"(r[3]) : "r"(addr));
}
__device__ __forceinline__ void mma16816(float* c, const uint32_t* a, const uint32_t* b) {
    asm volatile("mma.sync.aligned.m16n8k16.row.col.f32.bf16.bf16.f32 "
        "{%0,%1,%2,%3}, {%4,%5,%6,%7}, {%8,%9}, {%0,%1,%2,%3};"
        : "+f"(c[0]), "+f"(c[1]), "+f"(c[2]), "+f"(c[3])
        : "r"(a[0]), "r"(a[1]), "r"(a[2]), "r"(a[3]), "r"(b[0]), "r"(b[1]));
}
__device__ __forceinline__ void split2(float x, float y,
                                       __nv_bfloat162& hi, __nv_bfloat162& lo) {
    __nv_bfloat16 hx = __float2bfloat16(x), hy = __float2bfloat16(y);
    hi.x = hx; hi.y = hy;
    lo.x = __float2bfloat16(x - __bfloat162float(hx));
    lo.y = __float2bfloat16(y - __bfloat162float(hy));
}
__device__ __forceinline__ void pksplit(float x, float y, uint32_t& hi, uint32_t& lo) {
    __nv_bfloat162 H, L;
    split2(x, y, H, L);
    hi = *reinterpret_cast<uint32_t*>(&H);
    lo = *reinterpret_cast<uint32_t*>(&L);
}
#define CP16(dst, src) asm volatile("cp.async.cg.shared.global [%0], [%1], 16;" :: "r"(dst), "l"(src))
#define CPCOMMIT()     asm volatile("cp.async.commit_group;" ::: "memory")
#define CPWAIT0()      asm volatile("cp.async.wait_group 0;" ::: "memory")

// ---------------- fused fp32 -> bf16 hi/lo pre-split (x, w_qkv, w_out) ----------------
#define NX4 (B_*N_*E_/4)
#define NWQ4 (3*E_*E_/4)
#define NWO4 (E_*E_/4)
__global__ void conv_kernel(const float4* __restrict__ x4,
                            const float4* __restrict__ wq4,
                            const float4* __restrict__ wo4) {
    int idx = blockIdx.x * blockDim.x + threadIdx.x;
    const float4* src;
    __nv_bfloat162 *hi, *lo;
    int li;
    if (idx < NX4)              { src = x4;  li = idx;                 hi = (__nv_bfloat162*)g_xhi;  lo = (__nv_bfloat162*)g_xlo; }
    else if (idx < NX4+NWQ4)    { src = wq4; li = idx - NX4;           hi = (__nv_bfloat162*)g_wqhi; lo = (__nv_bfloat162*)g_wqlo; }
    else if (idx < NX4+NWQ4+NWO4){ src = wo4; li = idx - NX4 - NWQ4;   hi = (__nv_bfloat162*)g_wohi; lo = (__nv_bfloat162*)g_wolo; }
    else return;
    float4 v = src[li];
    __nv_bfloat162 h0, l0, h1, l1;
    split2(v.x, v.y, h0, l0); split2(v.z, v.w, h1, l1);
    hi[li*2] = h0; hi[li*2+1] = h1;
    lo[li*2] = l0; lo[li*2+1] = l1;
}

// ---------------- bias = U @ w_u^T + b_u, transposed to [B,H,N,N] ----------------
__global__ void bias_kernel(const float* __restrict__ U,
                            const float* __restrict__ w_u,
                            const float* __restrict__ b_u) {
    __shared__ float sw[H_*ID_];
    __shared__ float sb[H_];
    if (threadIdx.x < H_*ID_) sw[threadIdx.x] = w_u[threadIdx.x];
    if (threadIdx.x < H_)     sb[threadIdx.x] = b_u[threadIdx.x];
    __syncthreads();
    int idx = blockIdx.x * blockDim.x + threadIdx.x;
    if (idx >= B_*N_*N_) return;
    const float4* up = (const float4*)(U + (size_t)idx * ID_);
    float4 u0 = up[0], u1 = up[1];
    float u[8] = {u0.x,u0.y,u0.z,u0.w,u1.x,u1.y,u1.z,u1.w};
    int b  = idx / (N_*N_);
    int nm = idx - b * (N_*N_);
    #pragma unroll
    for (int h = 0; h < H_; h++) {
        float s = sb[h];
        #pragma unroll
        for (int i = 0; i < 8; i++) s += u[i] * sw[h*ID_ + i];
        g_bias[((size_t)(b*H_ + h)) * (N_*N_) + nm] = s;
    }
}

// ============ HMMA GEMM on pre-split bf16, cp.async, single sync per slab ============
#define TK 32
#define NKS (KDIM/TK)
#define MAT_B (128*40*2)
#define STG_B (4*MAT_B)
#define GEMM_SMEM (2*STG_B)

__global__ __launch_bounds__(256, 2)
void gemm_mma(const float* __restrict__ bias, int mode, float* __restrict__ out) {
    extern __shared__ char dsm[];
    const int t    = threadIdx.x;
    const int lane = t & 31;
    const int wid  = t >> 5;
    const int warpM = wid >> 2;
    const int warpN = wid & 3;
    const int rowBase = blockIdx.y * 128;
    const int colBase = blockIdx.x * 128;
    const uint32_t smb = smem_u32(dsm);

    const __nv_bfloat16 *Ah, *Al, *Wh, *Wl;
    if (mode == 0) { Ah = g_xhi; Al = g_xlo; Wh = g_wqhi; Wl = g_wqlo; }
    else           { Ah = g_ohi; Al = g_olo; Wh = g_wohi; Wl = g_wolo; }

    float acc[4][4][4];
    #pragma unroll
    for (int i = 0; i < 4; i++)
        #pragma unroll
        for (int j = 0; j < 4; j++)
            #pragma unroll
            for (int e = 0; e < 4; e++) acc[i][j][e] = 0.f;

    auto issue = [&](int s) {
        int k0 = s * TK;
        uint32_t st = smb + (s & 1)*STG_B;
        #pragma unroll
        for (int l = 0; l < 2; l++) {
            int f = t + l*256;
            int r = f >> 2, c = f & 3;
            uint32_t doff = (uint32_t)(r*80 + c*16);
            CP16(st + doff,           Ah + (size_t)(rowBase + r)*KDIM + k0 + c*8);
            CP16(st + MAT_B + doff,   Al + (size_t)(rowBase + r)*KDIM + k0 + c*8);
            CP16(st + 2*MAT_B + doff, Wh + (size_t)(colBase + r)*KDIM + k0 + c*8);
            CP16(st + 3*MAT_B + doff, Wl + (size_t)(colBase + r)*KDIM + k0 + c*8);
        }
    };

    issue(0);
    CPCOMMIT();

    for (int ks = 0; ks < NKS; ks++) {
        CPWAIT0();
        __syncthreads();                 // single barrier per slab
        if (ks + 1 < NKS) { issue(ks + 1); CPCOMMIT(); }

        uint32_t stg = smb + (ks & 1)*STG_B;
        #pragma unroll
        for (int k16 = 0; k16 < 2; k16++) {
            int colb = k16 * 16;
            uint32_t whi[4][2], wlo[4][2];
            {
                int l8  = lane & 7, sel = lane >> 3;
                #pragma unroll
                for (int np = 0; np < 2; np++) {
                    int wrow = warpN*32 + np*16 + (sel >> 1)*8 + l8;
                    int wcol = colb + (sel & 1)*8;
                    uint32_t off = (uint32_t)(wrow*80 + wcol*2);
                    uint32_t r[4];
                    ldsm4(r, stg + 2*MAT_B + off);
                    whi[np*2+0][0]=r[0]; whi[np*2+0][1]=r[1];
                    whi[np*2+1][0]=r[2]; whi[np*2+1][1]=r[3];
                    ldsm4(r, stg + 3*MAT_B + off);
                    wlo[np*2+0][0]=r[0]; wlo[np*2+0][1]=r[1];
                    wlo[np*2+1][0]=r[2]; wlo[np*2+1][1]=r[3];
                }
            }
            int r8 = lane & 7, half = (lane >> 3) & 1, kk = lane >> 4;
            #pragma unroll
            for (int mi = 0; mi < 4; mi++) {
                int arow = warpM*64 + mi*16 + half*8 + r8;
                int acol = colb + kk*8;
                uint32_t off = (uint32_t)(arow*80 + acol*2);
                uint32_t a[4];
                ldsm4(a, stg + off);
                #pragma unroll
                for (int ni = 0; ni < 4; ni++) mma16816(acc[mi][ni], a, whi[ni]);
                #pragma unroll
                for (int ni = 0; ni < 4; ni++) mma16816(acc[mi][ni], a, wlo[ni]);
                ldsm4(a, stg + MAT_B + off);
                #pragma unroll
                for (int ni = 0; ni < 4; ni++) mma16816(acc[mi][ni], a, whi[ni]);
            }
        }
    }

    const int gID = lane >> 2, tg = lane & 3;
    #pragma unroll
    for (int mi = 0; mi < 4; mi++) {
        #pragma unroll
        for (int ni = 0; ni < 4; ni++) {
            #pragma unroll
            for (int e2 = 0; e2 < 2; e2++) {
                int r = rowBase + warpM*64 + mi*16 + gID + e2*8;
                int c = colBase + warpN*32 + ni*8 + tg*2;
                float v0 = acc[mi][ni][e2*2+0] + __ldg(bias + c);
                float v1 = acc[mi][ni][e2*2+1] + __ldg(bias + c + 1);
                if (mode == 0) {
                    int bb = r >> 8, n = r & 255;
                    int sec = c >> 9;
                    int jj  = c & 511;
                    int h = jj >> 6, d = jj & 63;
                    size_t dst = ((size_t)((bb*H_ + h)*N_ + n))*D_ + d;
                    __nv_bfloat162 hi, lo;
                    if (sec == 0) {
                        split2(v0 * 0.125f, v1 * 0.125f, hi, lo);
                        *(__nv_bfloat162*)(g_qhi + dst) = hi;
                        *(__nv_bfloat162*)(g_qlo + dst) = lo;
                    } else if (sec == 1) {
                        split2(v0, v1, hi, lo);
                        *(__nv_bfloat162*)(g_khi + dst) = hi;
                        *(__nv_bfloat162*)(g_klo + dst) = lo;
                    } else {
                        split2(v0, v1, hi, lo);
                        *(__nv_bfloat162*)(g_vhi + dst) = hi;
                        *(__nv_bfloat162*)(g_vlo + dst) = lo;
                    }
                } else {
                    out[(size_t)r*E_ + c]     = v0;
                    out[(size_t)r*E_ + c + 1] = v1;
                }
            }
        }
    }
}

// ======== attention: persistent CTA per (b,h); K/V loaded once, 4 q-chunks ========
// dynamic smem 231424 B + static 256 B (s_inv) = 231680 <= 232448 limit.
// s_red ALIASES the first 1024 B of AT_OP (dead before OP partials are written).
#define KP 72
#define AT_KHI 0
#define AT_KLO 36864
#define AT_VHI 73728
#define AT_VLO 110592
#define AT_QHI 147456
#define AT_QLO 156672
#define AT_OP  165888
#define ATTN_SMEM 231424

__global__ __launch_bounds__(256)
void attn_kernel() {
    extern __shared__ char asm_[];
    __shared__ float s_inv[64];
    float (*s_red)[64] = (float (*)[64])(asm_ + AT_OP);   // aliases OP region

    const int bh = blockIdx.x;
    const int t  = threadIdx.x;
    const int lane = t & 31;
    const int wid  = t >> 5;
    const int warpM = wid >> 2;
    const int warpN = wid & 3;
    const int gID = lane >> 2, tg = lane & 3;
    const int b  = bh >> 3, h = bh & 7;
    const uint32_t smb = smem_u32(asm_);

    const uint4* khi = (const uint4*)(g_khi + (size_t)bh * N_ * D_);
    const uint4* klo = (const uint4*)(g_klo + (size_t)bh * N_ * D_);
    const uint4* vhi = (const uint4*)(g_vhi + (size_t)bh * N_ * D_);
    const uint4* vlo = (const uint4*)(g_vlo + (size_t)bh * N_ * D_);
    const float* bbase = g_bias + (size_t)bh * N_ * N_;

    // K,V once per CTA
    for (int f = t; f < 2048; f += 256) {
        int row = f >> 3, c8 = f & 7;
        int off = row*144 + c8*16;
        *(uint4*)(asm_ + AT_KHI + off) = khi[f];
        *(uint4*)(asm_ + AT_KLO + off) = klo[f];
        *(uint4*)(asm_ + AT_VHI + off) = vhi[f];
        *(uint4*)(asm_ + AT_VLO + off) = vlo[f];
    }

    for (int qc = 0; qc < 4; qc++) {
        const int q0 = qc << 6;
        const uint4* qhi = (const uint4*)(g_qhi + (size_t)bh * N_ * D_ + (size_t)q0 * D_);
        const uint4* qlo = (const uint4*)(g_qlo + (size_t)bh * N_ * D_ + (size_t)q0 * D_);
        for (int f = t; f < 512; f += 256) {
            int row = f >> 3, c8 = f & 7;
            int off = row*144 + c8*16;
            *(uint4*)(asm_ + AT_QHI + off) = qhi[f];
            *(uint4*)(asm_ + AT_QLO + off) = qlo[f];
        }
        __syncthreads();

        // S = Q K^T
        float acc[2][8][4];
        #pragma unroll
        for (int i = 0; i < 2; i++)
            #pragma unroll
            for (int j = 0; j < 8; j++)
                #pragma unroll
                for (int e = 0; e < 4; e++) acc[i][j][e] = 0.f;
        {
            const int l8 = lane & 7, sel = lane >> 3;
            const int r8 = lane & 7, halfq = (lane >> 3) & 1, k8 = lane >> 4;
            #pragma unroll
            for (int kk = 0; kk < 4; kk++) {
                uint32_t bhi[8][2], blo[8][2];
                #pragma unroll
                for (int np = 0; np < 4; np++) {
                    int wrow = warpN*64 + np*16 + (sel >> 1)*8 + l8;
                    int wcol = kk*16 + (sel & 1)*8;
                    uint32_t off = (uint32_t)((wrow*KP + wcol)*2);
                    uint32_t r[4];
                    ldsm4(r, smb + AT_KHI + off);
                    bhi[np*2+0][0]=r[0]; bhi[np*2+0][1]=r[1];
                    bhi[np*2+1][0]=r[2]; bhi[np*2+1][1]=r[3];
                    ldsm4(r, smb + AT_KLO + off);
                    blo[np*2+0][0]=r[0]; blo[np*2+0][1]=r[1];
                    blo[np*2+1][0]=r[2]; blo[np*2+1][1]=r[3];
                }
                #pragma unroll
                for (int mi = 0; mi < 2; mi++) {
                    int arow = warpM*32 + mi*16 + halfq*8 + r8;
                    int acol = kk*16 + k8*8;
                    uint32_t off = (uint32_t)((arow*KP + acol)*2);
                    uint32_t a[4];
                    ldsm4(a, smb + AT_QHI + off);
                    #pragma unroll
                    for (int nj = 0; nj < 8; nj++) mma16816(acc[mi][nj], a, bhi[nj]);
                    #pragma unroll
                    for (int nj = 0; nj < 8; nj++) mma16816(acc[mi][nj], a, blo[nj]);
                    ldsm4(a, smb + AT_QLO + off);
                    #pragma unroll
                    for (int nj = 0; nj < 8; nj++) mma16816(acc[mi][nj], a, bhi[nj]);
                }
            }
        }

        // bias
        #pragma unroll
        for (int mi = 0; mi < 2; mi++) {
            int r0 = q0 + warpM*32 + mi*16 + gID;
            #pragma unroll
            for (int nj = 0; nj < 8; nj++) {
                int c = warpN*64 + nj*8 + tg*2;
                float2 b0 = *(const float2*)(bbase + (size_t)r0*N_ + c);
                float2 b1 = *(const float2*)(bbase + (size_t)(r0+8)*N_ + c);
                acc[mi][nj][0] += b0.x; acc[mi][nj][1] += b0.y;
                acc[mi][nj][2] += b1.x; acc[mi][nj][3] += b1.y;
            }
        }

        // softmax (s_red aliases OP region — dead there until after PV)
        #pragma unroll
        for (int mi = 0; mi < 2; mi++)
            #pragma unroll
            for (int h2 = 0; h2 < 2; h2++) {
                float m = -1e30f;
                #pragma unroll
                for (int nj = 0; nj < 8; nj++) {
                    m = fmaxf(m, acc[mi][nj][h2*2+0]);
                    m = fmaxf(m, acc[mi][nj][h2*2+1]);
                }
                m = fmaxf(m, __shfl_xor_sync(0xffffffffu, m, 1));
                m = fmaxf(m, __shfl_xor_sync(0xffffffffu, m, 2));
                if (tg == 0) s_red[warpN][warpM*32 + mi*16 + gID + h2*8] = m;
            }
        __syncthreads();
        float psum[2][2];
        #pragma unroll
        for (int mi = 0; mi < 2; mi++)
            #pragma unroll
            for (int h2 = 0; h2 < 2; h2++) {
                int row = warpM*32 + mi*16 + gID + h2*8;
                float fm = fmaxf(fmaxf(s_red[0][row], s_red[1][row]),
                                 fmaxf(s_red[2][row], s_red[3][row]));
                float s = 0.f;
                #pragma unroll
                for (int nj = 0; nj < 8; nj++) {
                    float p0 = __expf(acc[mi][nj][h2*2+0] - fm);
                    float p1 = __expf(acc[mi][nj][h2*2+1] - fm);
                    acc[mi][nj][h2*2+0] = p0; acc[mi][nj][h2*2+1] = p1;
                    s += p0 + p1;
                }
                s += __shfl_xor_sync(0xffffffffu, s, 1);
                s += __shfl_xor_sync(0xffffffffu, s, 2);
                psum[mi][h2] = s;
            }
        __syncthreads();
        #pragma unroll
        for (int mi = 0; mi < 2; mi++)
            #pragma unroll
            for (int h2 = 0; h2 < 2; h2++)
                if (tg == 0) s_red[warpN][warpM*32 + mi*16 + gID + h2*8] = psum[mi][h2];
        __syncthreads();
        if (warpN == 0 && tg == 0) {
            #pragma unroll
            for (int mi = 0; mi < 2; mi++)
                #pragma unroll
                for (int h2 = 0; h2 < 2; h2++) {
                    int row = warpM*32 + mi*16 + gID + h2*8;
                    s_inv[row] = 1.0f / (s_red[0][row] + s_red[1][row]
                                       + s_red[2][row] + s_red[3][row]);
                }
        }

        // pack P
        uint32_t phi[2][4][4], plo[2][4][4];
        #pragma unroll
        for (int mi = 0; mi < 2; mi++)
            #pragma unroll
            for (int kk = 0; kk < 4; kk++)
                #pragma unroll
                for (int j = 0; j < 2; j++) {
                    float* cc = acc[mi][kk*2+j];
                    pksplit(cc[0], cc[1], phi[mi][kk][j*2+0], plo[mi][kk][j*2+0]);
                    pksplit(cc[2], cc[3], phi[mi][kk][j*2+1], plo[mi][kk][j*2+1]);
                }

        // O_partial = P * V
        float oacc[2][8][4];
        #pragma unroll
        for (int i = 0; i < 2; i++)
            #pragma unroll
            for (int j = 0; j < 8; j++)
                #pragma unroll
                for (int e = 0; e < 4; e++) oacc[i][j][e] = 0.f;
        {
            const int l8 = lane & 7, sel = lane >> 3;
            #pragma unroll
            for (int kk = 0; kk < 4; kk++) {
                #pragma unroll
                for (int ng = 0; ng < 4; ng++) {
                    int vrow = warpN*64 + kk*16 + (sel & 1)*8 + l8;
                    int vcol = ng*16 + (sel >> 1)*8;
                    uint32_t off = (uint32_t)((vrow*KP + vcol)*2);
                    uint32_t bh4[4], bl4[4];
                    ldsm4t(bh4, smb + AT_VHI + off);
                    ldsm4t(bl4, smb + AT_VLO + off);
                    #pragma unroll
                    for (int mi = 0; mi < 2; mi++)
                        #pragma unroll
                        for (int j = 0; j < 2; j++) {
                            mma16816(oacc[mi][ng*2+j], phi[mi][kk], bh4 + j*2);
                            mma16816(oacc[mi][ng*2+j], phi[mi][kk], bl4 + j*2);
                            mma16816(oacc[mi][ng*2+j], plo[mi][kk], bh4 + j*2);
                        }
                }
            }
        }

        // cross-warp reduce + store (s_red dead now; OP overwrites it)
        __syncthreads();
        float* op = (float*)(asm_ + AT_OP) + wid*2048;
        #pragma unroll
        for (int mi = 0; mi < 2; mi++)
            #pragma unroll
            for (int nd = 0; nd < 8; nd++) {
                int c = nd*8 + tg*2;
                op[(mi*16 + gID    )*64 + c    ] = oacc[mi][nd][0];
                op[(mi*16 + gID    )*64 + c + 1] = oacc[mi][nd][1];
                op[(mi*16 + gID + 8)*64 + c    ] = oacc[mi][nd][2];
                op[(mi*16 + gID + 8)*64 + c + 1] = oacc[mi][nd][3];
            }
        __syncthreads();
        for (int f = t; f < 1024; f += 256) {
            int R = f >> 4, c4 = (f & 15) * 4;
            int wg = (R >> 5) * 4;
            const float* base0 = (const float*)(asm_ + AT_OP);
            float4 s = make_float4(0.f, 0.f, 0.f, 0.f);
            #pragma unroll
            for (int w = 0; w < 4; w++) {
                float4 v = *(const float4*)(base0 + (wg + w)*2048 + (R & 31)*64 + c4);
                s.x += v.x; s.y += v.y; s.z += v.z; s.w += v.w;
            }
            float inv = s_inv[R];
            s.x *= inv; s.y *= inv; s.z *= inv; s.w *= inv;
            __nv_bfloat162 h0, l0, h1, l1;
            split2(s.x, s.y, h0, l0); split2(s.z, s.w, h1, l1);
            size_t dst = ((size_t)(b*N_) + q0 + R)*E_ + h*D_ + c4;
            *(__nv_bfloat162*)(g_ohi + dst)     = h0;
            *(__nv_bfloat162*)(g_ohi + dst + 2) = h1;
            *(__nv_bfloat162*)(g_olo + dst)     = l0;
            *(__nv_bfloat162*)(g_olo + dst + 2) = l1;
        }
        __syncthreads();   // before next chunk's Q overwrite / s_red reuse
    }
}

// ---------------- launcher (all sequential, default stream) ----------------
extern "C" void kernel_launch(void* const* d_in, const int* in_sizes, int n_in,
                              void* d_out, int out_size) {
    const float* x     = (const float*)d_in[0];
    const float* U     = (const float*)d_in[1];
    const float* w_qkv = (const float*)d_in[2];
    const float* b_qkv = (const float*)d_in[3];
    const float* w_out = (const float*)d_in[4];
    const float* b_out = (const float*)d_in[5];
    const float* w_u   = (const float*)d_in[6];
    const float* b_u   = (const float*)d_in[7];
    float* out = (float*)d_out;

    cudaFuncSetAttribute(gemm_mma, cudaFuncAttributeMaxDynamicSharedMemorySize, GEMM_SMEM);
    cudaFuncSetAttribute(attn_kernel, cudaFuncAttributeMaxDynamicSharedMemorySize, ATTN_SMEM);

    conv_kernel<<<(NX4+NWQ4+NWO4 + 255)/256, 256>>>((const float4*)x,
                                                    (const float4*)w_qkv,
                                                    (const float4*)w_out);
    bias_kernel<<<(B_*N_*N_ + 255)/256, 256>>>(U, w_u, b_u);

    { dim3 g(1536/128, (B_*N_)/128); gemm_mma<<<g, 256, GEMM_SMEM>>>(b_qkv, 0, nullptr); }

    attn_kernel<<<B_*H_, 256, ATTN_SMEM>>>();

    { dim3 g(512/128, (B_*N_)/128); gemm_mma<<<g, 256, GEMM_SMEM>>>(b_out, 1, out); }
}

// round 11
// speedup vs baseline: 1.1128x; 1.1128x over previous
#include <cuda_runtime.h>
#include <cuda_bf16.h>
#include <cstdint>
#include <math.h>

#define B_   32
#define N_   256
#define E_   512
#define H_   8
#define D_   64
#define ID_  8
#define KDIM 512

// ---------------- device-global scratch (alloc-free), all bf16 hi/lo ----------------
__device__ __nv_bfloat16 g_xhi[(size_t)B_*N_*E_],  g_xlo[(size_t)B_*N_*E_];
__device__ __nv_bfloat16 g_wqhi[(size_t)3*E_*E_],  g_wqlo[(size_t)3*E_*E_];
__device__ __nv_bfloat16 g_wohi[(size_t)E_*E_],    g_wolo[(size_t)E_*E_];
__device__ __nv_bfloat16 g_qhi[(size_t)B_*H_*N_*D_], g_qlo[(size_t)B_*H_*N_*D_];
__device__ __nv_bfloat16 g_khi[(size_t)B_*H_*N_*D_], g_klo[(size_t)B_*H_*N_*D_];
__device__ __nv_bfloat16 g_vhi[(size_t)B_*H_*N_*D_], g_vlo[(size_t)B_*H_*N_*D_];
__device__ __nv_bfloat16 g_ohi[(size_t)B_*N_*E_],  g_olo[(size_t)B_*N_*E_];
__device__ float g_bias[(size_t)B_*H_*N_*N_];

// ================= helpers =================
__device__ __forceinline__ uint32_t smem_u32(const void* p) {
    uint32_t a;
    asm("{ .reg .u64 t; cvta.to.shared.u64 t, %1; cvt.u32.u64 %0, t; }" : "=r"(a) : "l"(p));
    return a;
}
__device__ __forceinline__ void ldsm4(uint32_t* r, uint32_t addr) {
    asm volatile("ldmatrix.sync.aligned.m8n8.x4.shared.b16 {%0,%1,%2,%3}, [%4];"
        : "=r"(r[0]), "=r"(r[1]), "=r"(r[2]), "=r"(r[3]) : "r"(addr));
}
__device__ __forceinline__ void ldsm4t(uint32_t* r, uint32_t addr) {
    asm volatile("ldmatrix.sync.aligned.m8n8.x4.trans.shared.b16 {%0,%1,%2,%3}, [%4];"
        : "=r"(r[0]), "=r"(r[1]), "=r"(r[2]), "=r"(r[3]) : "r"(addr));
}
__device__ __forceinline__ void mma16816(float* c, const uint32_t* a, const uint32_t* b) {
    asm volatile("mma.sync.aligned.m16n8k16.row.col.f32.bf16.bf16.f32 "
        "{%0,%1,%2,%3}, {%4,%5,%6,%7}, {%8,%9}, {%0,%1,%2,%3};"
        : "+f"(c[0]), "+f"(c[1]), "+f"(c[2]), "+f"(c[3])
        : "r"(a[0]), "r"(a[1]), "r"(a[2]), "r"(a[3]), "r"(b[0]), "r"(b[1]));
}
__device__ __forceinline__ void split2(float x, float y,
                                       __nv_bfloat162& hi, __nv_bfloat162& lo) {
    __nv_bfloat16 hx = __float2bfloat16(x), hy = __float2bfloat16(y);
    hi.x = hx; hi.y = hy;
    lo.x = __float2bfloat16(x - __bfloat162float(hx));
    lo.y = __float2bfloat16(y - __bfloat162float(hy));
}
__device__ __forceinline__ void pksplit(float x, float y, uint32_t& hi, uint32_t& lo) {
    __nv_bfloat162 H, L;
    split2(x, y, H, L);
    hi = *reinterpret_cast<uint32_t*>(&H);
    lo = *reinterpret_cast<uint32_t*>(&L);
}
#define CP16(dst, src) asm volatile("cp.async.cg.shared.global [%0], [%1], 16;" :: "r"(dst), "l"(src))
#define CPCOMMIT()     asm volatile("cp.async.commit_group;" ::: "memory")
#define CPWAIT0()      asm volatile("cp.async.wait_group 0;" ::: "memory")

// ---------------- fused fp32 -> bf16 hi/lo pre-split (x, w_qkv, w_out) ----------------
#define NX4 (B_*N_*E_/4)
#define NWQ4 (3*E_*E_/4)
#define NWO4 (E_*E_/4)
__global__ void conv_kernel(const float4* __restrict__ x4,
                            const float4* __restrict__ wq4,
                            const float4* __restrict__ wo4) {
    int idx = blockIdx.x * blockDim.x + threadIdx.x;
    const float4* src;
    __nv_bfloat162 *hi, *lo;
    int li;
    if (idx < NX4)              { src = x4;  li = idx;                 hi = (__nv_bfloat162*)g_xhi;  lo = (__nv_bfloat162*)g_xlo; }
    else if (idx < NX4+NWQ4)    { src = wq4; li = idx - NX4;           hi = (__nv_bfloat162*)g_wqhi; lo = (__nv_bfloat162*)g_wqlo; }
    else if (idx < NX4+NWQ4+NWO4){ src = wo4; li = idx - NX4 - NWQ4;   hi = (__nv_bfloat162*)g_wohi; lo = (__nv_bfloat162*)g_wolo; }
    else return;
    float4 v = src[li];
    __nv_bfloat162 h0, l0, h1, l1;
    split2(v.x, v.y, h0, l0); split2(v.z, v.w, h1, l1);
    hi[li*2] = h0; hi[li*2+1] = h1;
    lo[li*2] = l0; lo[li*2+1] = l1;
}

// ---------------- bias = U @ w_u^T + b_u, transposed to [B,H,N,N] ----------------
__global__ void bias_kernel(const float* __restrict__ U,
                            const float* __restrict__ w_u,
                            const float* __restrict__ b_u) {
    __shared__ float sw[H_*ID_];
    __shared__ float sb[H_];
    if (threadIdx.x < H_*ID_) sw[threadIdx.x] = w_u[threadIdx.x];
    if (threadIdx.x < H_)     sb[threadIdx.x] = b_u[threadIdx.x];
    __syncthreads();
    int idx = blockIdx.x * blockDim.x + threadIdx.x;
    if (idx >= B_*N_*N_) return;
    const float4* up = (const float4*)(U + (size_t)idx * ID_);
    float4 u0 = up[0], u1 = up[1];
    float u[8] = {u0.x,u0.y,u0.z,u0.w,u1.x,u1.y,u1.z,u1.w};
    int b  = idx / (N_*N_);
    int nm = idx - b * (N_*N_);
    #pragma unroll
    for (int h = 0; h < H_; h++) {
        float s = sb[h];
        #pragma unroll
        for (int i = 0; i < 8; i++) s += u[i] * sw[h*ID_ + i];
        g_bias[((size_t)(b*H_ + h)) * (N_*N_) + nm] = s;
    }
}

// ============ HMMA GEMM on pre-split bf16, cp.async, single sync per slab ============
#define TK 32
#define NKS (KDIM/TK)
#define MAT_B (128*40*2)
#define STG_B (4*MAT_B)
#define GEMM_SMEM (2*STG_B)

__global__ __launch_bounds__(256, 2)
void gemm_mma(const float* __restrict__ bias, int mode, float* __restrict__ out) {
    extern __shared__ char dsm[];
    const int t    = threadIdx.x;
    const int lane = t & 31;
    const int wid  = t >> 5;
    const int warpM = wid >> 2;
    const int warpN = wid & 3;
    const int rowBase = blockIdx.y * 128;
    const int colBase = blockIdx.x * 128;
    const uint32_t smb = smem_u32(dsm);

    const __nv_bfloat16 *Ah, *Al, *Wh, *Wl;
    if (mode == 0) { Ah = g_xhi; Al = g_xlo; Wh = g_wqhi; Wl = g_wqlo; }
    else           { Ah = g_ohi; Al = g_olo; Wh = g_wohi; Wl = g_wolo; }

    float acc[4][4][4];
    #pragma unroll
    for (int i = 0; i < 4; i++)
        #pragma unroll
        for (int j = 0; j < 4; j++)
            #pragma unroll
            for (int e = 0; e < 4; e++) acc[i][j][e] = 0.f;

    auto issue = [&](int s) {
        int k0 = s * TK;
        uint32_t st = smb + (s & 1)*STG_B;
        #pragma unroll
        for (int l = 0; l < 2; l++) {
            int f = t + l*256;
            int r = f >> 2, c = f & 3;
            uint32_t doff = (uint32_t)(r*80 + c*16);
            CP16(st + doff,           Ah + (size_t)(rowBase + r)*KDIM + k0 + c*8);
            CP16(st + MAT_B + doff,   Al + (size_t)(rowBase + r)*KDIM + k0 + c*8);
            CP16(st + 2*MAT_B + doff, Wh + (size_t)(colBase + r)*KDIM + k0 + c*8);
            CP16(st + 3*MAT_B + doff, Wl + (size_t)(colBase + r)*KDIM + k0 + c*8);
        }
    };

    issue(0);
    CPCOMMIT();

    for (int ks = 0; ks < NKS; ks++) {
        CPWAIT0();
        __syncthreads();
        if (ks + 1 < NKS) { issue(ks + 1); CPCOMMIT(); }

        uint32_t stg = smb + (ks & 1)*STG_B;
        #pragma unroll
        for (int k16 = 0; k16 < 2; k16++) {
            int colb = k16 * 16;
            uint32_t whi[4][2], wlo[4][2];
            {
                int l8  = lane & 7, sel = lane >> 3;
                #pragma unroll
                for (int np = 0; np < 2; np++) {
                    int wrow = warpN*32 + np*16 + (sel >> 1)*8 + l8;
                    int wcol = colb + (sel & 1)*8;
                    uint32_t off = (uint32_t)(wrow*80 + wcol*2);
                    uint32_t r[4];
                    ldsm4(r, stg + 2*MAT_B + off);
                    whi[np*2+0][0]=r[0]; whi[np*2+0][1]=r[1];
                    whi[np*2+1][0]=r[2]; whi[np*2+1][1]=r[3];
                    ldsm4(r, stg + 3*MAT_B + off);
                    wlo[np*2+0][0]=r[0]; wlo[np*2+0][1]=r[1];
                    wlo[np*2+1][0]=r[2]; wlo[np*2+1][1]=r[3];
                }
            }
            int r8 = lane & 7, half = (lane >> 3) & 1, kk = lane >> 4;
            #pragma unroll
            for (int mi = 0; mi < 4; mi++) {
                int arow = warpM*64 + mi*16 + half*8 + r8;
                int acol = colb + kk*8;
                uint32_t off = (uint32_t)(arow*80 + acol*2);
                uint32_t a[4];
                ldsm4(a, stg + off);
                #pragma unroll
                for (int ni = 0; ni < 4; ni++) mma16816(acc[mi][ni], a, whi[ni]);
                #pragma unroll
                for (int ni = 0; ni < 4; ni++) mma16816(acc[mi][ni], a, wlo[ni]);
                ldsm4(a, stg + MAT_B + off);
                #pragma unroll
                for (int ni = 0; ni < 4; ni++) mma16816(acc[mi][ni], a, whi[ni]);
            }
        }
    }

    const int gID = lane >> 2, tg = lane & 3;
    #pragma unroll
    for (int mi = 0; mi < 4; mi++) {
        #pragma unroll
        for (int ni = 0; ni < 4; ni++) {
            #pragma unroll
            for (int e2 = 0; e2 < 2; e2++) {
                int r = rowBase + warpM*64 + mi*16 + gID + e2*8;
                int c = colBase + warpN*32 + ni*8 + tg*2;
                float v0 = acc[mi][ni][e2*2+0] + __ldg(bias + c);
                float v1 = acc[mi][ni][e2*2+1] + __ldg(bias + c + 1);
                if (mode == 0) {
                    int bb = r >> 8, n = r & 255;
                    int sec = c >> 9;
                    int jj  = c & 511;
                    int h = jj >> 6, d = jj & 63;
                    size_t dst = ((size_t)((bb*H_ + h)*N_ + n))*D_ + d;
                    __nv_bfloat162 hi, lo;
                    if (sec == 0) {
                        split2(v0 * 0.125f, v1 * 0.125f, hi, lo);
                        *(__nv_bfloat162*)(g_qhi + dst) = hi;
                        *(__nv_bfloat162*)(g_qlo + dst) = lo;
                    } else if (sec == 1) {
                        split2(v0, v1, hi, lo);
                        *(__nv_bfloat162*)(g_khi + dst) = hi;
                        *(__nv_bfloat162*)(g_klo + dst) = lo;
                    } else {
                        split2(v0, v1, hi, lo);
                        *(__nv_bfloat162*)(g_vhi + dst) = hi;
                        *(__nv_bfloat162*)(g_vlo + dst) = lo;
                    }
                } else {
                    out[(size_t)r*E_ + c]     = v0;
                    out[(size_t)r*E_ + c + 1] = v1;
                }
            }
        }
    }
}

// ======== attention v2: warp owns 16 q-rows x ALL 256 keys; zero cross-warp traffic ========
// smem: KHI/KLO [256][72], VHI/VLO [256][72], QHI/QLO [128][72] = 184320 B dynamic.
// 1 CTA per (b,h); 2 passes x 128 q-rows; 8 warps x 16 rows.
#define KP 72
#define AT_KHI 0
#define AT_KLO 36864
#define AT_VHI 73728
#define AT_VLO 110592
#define AT_QHI 147456
#define AT_QLO 165888
#define ATTN_SMEM 184320

__global__ __launch_bounds__(256)
void attn_kernel() {
    extern __shared__ char asm_[];
    const int bh = blockIdx.x;
    const int t  = threadIdx.x;
    const int lane = t & 31;
    const int wid  = t >> 5;
    const int gID = lane >> 2, tg = lane & 3;
    const int b  = bh >> 3, h = bh & 7;
    const uint32_t smb = smem_u32(asm_);

    const uint4* khi = (const uint4*)(g_khi + (size_t)bh * N_ * D_);
    const uint4* klo = (const uint4*)(g_klo + (size_t)bh * N_ * D_);
    const uint4* vhi = (const uint4*)(g_vhi + (size_t)bh * N_ * D_);
    const uint4* vlo = (const uint4*)(g_vlo + (size_t)bh * N_ * D_);
    const float* bbase = g_bias + (size_t)bh * N_ * N_;

    // K,V resident for the whole CTA
    for (int f = t; f < 2048; f += 256) {
        int row = f >> 3, c8 = f & 7;
        int off = row*144 + c8*16;
        *(uint4*)(asm_ + AT_KHI + off) = khi[f];
        *(uint4*)(asm_ + AT_KLO + off) = klo[f];
        *(uint4*)(asm_ + AT_VHI + off) = vhi[f];
        *(uint4*)(asm_ + AT_VLO + off) = vlo[f];
    }

    const int l8 = lane & 7, sel = lane >> 3;
    const int r8 = lane & 7, halfq = (lane >> 3) & 1, k8 = lane >> 4;

    for (int pass = 0; pass < 2; pass++) {
        const int q0 = pass * 128;
        const uint4* qhi = (const uint4*)(g_qhi + (size_t)bh * N_ * D_ + (size_t)q0 * D_);
        const uint4* qlo = (const uint4*)(g_qlo + (size_t)bh * N_ * D_ + (size_t)q0 * D_);
        for (int f = t; f < 1024; f += 256) {
            int row = f >> 3, c8 = f & 7;
            int off = row*144 + c8*16;
            *(uint4*)(asm_ + AT_QHI + off) = qhi[f];
            *(uint4*)(asm_ + AT_QLO + off) = qlo[f];
        }
        __syncthreads();

        // ---- S(16 x 256) = Q K^T, 3-term split; warp-private accumulator ----
        float acc[32][4];
        #pragma unroll
        for (int j = 0; j < 32; j++)
            #pragma unroll
            for (int e = 0; e < 4; e++) acc[j][e] = 0.f;

        #pragma unroll
        for (int kk = 0; kk < 4; kk++) {
            int arow = wid*16 + halfq*8 + r8;
            int acol = kk*16 + k8*8;
            uint32_t aoff = (uint32_t)((arow*KP + acol)*2);
            uint32_t ahi[4], alo[4];
            ldsm4(ahi, smb + AT_QHI + aoff);
            ldsm4(alo, smb + AT_QLO + aoff);
            #pragma unroll
            for (int np = 0; np < 16; np++) {
                int wrow = np*16 + (sel >> 1)*8 + l8;
                int wcol = kk*16 + (sel & 1)*8;
                uint32_t koff = (uint32_t)((wrow*KP + wcol)*2);
                uint32_t kf[4];
                ldsm4(kf, smb + AT_KHI + koff);
                mma16816(acc[np*2+0], ahi, kf);
                mma16816(acc[np*2+1], ahi, kf + 2);
                mma16816(acc[np*2+0], alo, kf);
                mma16816(acc[np*2+1], alo, kf + 2);
                ldsm4(kf, smb + AT_KLO + koff);
                mma16816(acc[np*2+0], ahi, kf);
                mma16816(acc[np*2+1], ahi, kf + 2);
            }
        }

        // ---- bias add (rows owned by this warp) ----
        {
            int r0 = q0 + wid*16 + gID;
            #pragma unroll
            for (int nj = 0; nj < 32; nj++) {
                int c = nj*8 + tg*2;
                float2 b0 = *(const float2*)(bbase + (size_t)r0*N_ + c);
                float2 b1 = *(const float2*)(bbase + (size_t)(r0+8)*N_ + c);
                acc[nj][0] += b0.x; acc[nj][1] += b0.y;
                acc[nj][2] += b1.x; acc[nj][3] += b1.y;
            }
        }

        // ---- softmax, fully warp-local (reduce over tg lanes only) ----
        float inv[2];
        #pragma unroll
        for (int h2 = 0; h2 < 2; h2++) {
            float m = -1e30f;
            #pragma unroll
            for (int nj = 0; nj < 32; nj++) {
                m = fmaxf(m, acc[nj][h2*2+0]);
                m = fmaxf(m, acc[nj][h2*2+1]);
            }
            m = fmaxf(m, __shfl_xor_sync(0xffffffffu, m, 1));
            m = fmaxf(m, __shfl_xor_sync(0xffffffffu, m, 2));
            float s = 0.f;
            #pragma unroll
            for (int nj = 0; nj < 32; nj++) {
                float p0 = __expf(acc[nj][h2*2+0] - m);
                float p1 = __expf(acc[nj][h2*2+1] - m);
                acc[nj][h2*2+0] = p0; acc[nj][h2*2+1] = p1;
                s += p0 + p1;
            }
            s += __shfl_xor_sync(0xffffffffu, s, 1);
            s += __shfl_xor_sync(0xffffffffu, s, 2);
            inv[h2] = 1.0f / s;
        }

        // ---- pack P in place (acc layout == A-fragment layout) ----
        uint32_t (*pk)[4] = reinterpret_cast<uint32_t(*)[4]>(acc);
        #pragma unroll
        for (int nj = 0; nj < 32; nj++) {
            float c0 = acc[nj][0], c1 = acc[nj][1], c2 = acc[nj][2], c3 = acc[nj][3];
            uint32_t h01, l01, h23, l23;
            pksplit(c0, c1, h01, l01);
            pksplit(c2, c3, h23, l23);
            pk[nj][0] = h01; pk[nj][1] = h23; pk[nj][2] = l01; pk[nj][3] = l23;
        }

        // ---- O(16 x 64) = P V via ldmatrix.trans on V ----
        float oacc[8][4];
        #pragma unroll
        for (int j = 0; j < 8; j++)
            #pragma unroll
            for (int e = 0; e < 4; e++) oacc[j][e] = 0.f;

        #pragma unroll
        for (int kc = 0; kc < 16; kc++) {
            uint32_t pa[4] = { pk[2*kc][0], pk[2*kc][1], pk[2*kc+1][0], pk[2*kc+1][1] };
            uint32_t pl[4] = { pk[2*kc][2], pk[2*kc][3], pk[2*kc+1][2], pk[2*kc+1][3] };
            #pragma unroll
            for (int ng = 0; ng < 4; ng++) {
                int vrow = kc*16 + (sel & 1)*8 + l8;
                int vcol = ng*16 + (sel >> 1)*8;
                uint32_t voff = (uint32_t)((vrow*KP + vcol)*2);
                uint32_t vh[4], vl[4];
                ldsm4t(vh, smb + AT_VHI + voff);
                ldsm4t(vl, smb + AT_VLO + voff);
                #pragma unroll
                for (int j = 0; j < 2; j++) {
                    mma16816(oacc[ng*2+j], pa, vh + j*2);
                    mma16816(oacc[ng*2+j], pa, vl + j*2);
                    mma16816(oacc[ng*2+j], pl, vh + j*2);
                }
            }
        }

        // ---- normalize + store o as bf16 hi/lo directly (no cross-warp reduce) ----
        {
            size_t row0 = (size_t)(b*N_ + q0 + wid*16 + gID) * E_ + h*D_;
            size_t row1 = row0 + 8*E_;
            #pragma unroll
            for (int nd = 0; nd < 8; nd++) {
                int c = nd*8 + tg*2;
                __nv_bfloat162 h0, l0;
                split2(oacc[nd][0]*inv[0], oacc[nd][1]*inv[0], h0, l0);
                *(__nv_bfloat162*)(g_ohi + row0 + c) = h0;
                *(__nv_bfloat162*)(g_olo + row0 + c) = l0;
                split2(oacc[nd][2]*inv[1], oacc[nd][3]*inv[1], h0, l0);
                *(__nv_bfloat162*)(g_ohi + row1 + c) = h0;
                *(__nv_bfloat162*)(g_olo + row1 + c) = l0;
            }
        }
        __syncthreads();   // before next pass overwrites Q
    }
}

// ---------------- launcher (all sequential, default stream) ----------------
extern "C" void kernel_launch(void* const* d_in, const int* in_sizes, int n_in,
                              void* d_out, int out_size) {
    const float* x     = (const float*)d_in[0];
    const float* U     = (const float*)d_in[1];
    const float* w_qkv = (const float*)d_in[2];
    const float* b_qkv = (const float*)d_in[3];
    const float* w_out = (const float*)d_in[4];
    const float* b_out = (const float*)d_in[5];
    const float* w_u   = (const float*)d_in[6];
    const float* b_u   = (const float*)d_in[7];
    float* out = (float*)d_out;

    cudaFuncSetAttribute(gemm_mma, cudaFuncAttributeMaxDynamicSharedMemorySize, GEMM_SMEM);
    cudaFuncSetAttribute(attn_kernel, cudaFuncAttributeMaxDynamicSharedMemorySize, ATTN_SMEM);

    conv_kernel<<<(NX4+NWQ4+NWO4 + 255)/256, 256>>>((const float4*)x,
                                                    (const float4*)w_qkv,
                                                    (const float4*)w_out);
    bias_kernel<<<(B_*N_*N_ + 255)/256, 256>>>(U, w_u, b_u);

    { dim3 g(1536/128, (B_*N_)/128); gemm_mma<<<g, 256, GEMM_SMEM>>>(b_qkv, 0, nullptr); }

    attn_kernel<<<B_*H_, 256, ATTN_SMEM>>>();

    { dim3 g(512/128, (B_*N_)/128); gemm_mma<<<g, 256, GEMM_SMEM>>>(b_out, 1, out); }
}